// round 14
// baseline (speedup 1.0000x reference)
#include <cuda_runtime.h>
#include <math.h>

#define GSZ   200
#define G2    40000
#define NPT   128
#define KB    10     // grid cells per block (divides GSZ -> one lat row per block)

typedef unsigned long long u64;

__device__ int g_best;   // packed (num<<16)|(39999-k); reset to 0 by kfinal

// ---------------- f32x2 helpers (per-element IEEE rn) -----------------------
__device__ __forceinline__ u64 pk(float a, float b) {
    u64 r; asm("mov.b64 %0, {%1, %2};" : "=l"(r) : "f"(a), "f"(b)); return r;
}
__device__ __forceinline__ void upk(u64 v, float& a, float& b) {
    asm("mov.b64 {%0, %1}, %2;" : "=f"(a), "=f"(b) : "l"(v));
}
__device__ __forceinline__ u64 fma2(u64 a, u64 b, u64 c) {
    u64 r; asm("fma.rn.f32x2 %0, %1, %2, %3;" : "=l"(r) : "l"(a), "l"(b), "l"(c)); return r;
}

// ---------------------------------------------------------------------------
// XLA f32 tanh (Eigen rational) — exact scalar form (kfinal only)
// ---------------------------------------------------------------------------
__device__ __forceinline__ float xla_tanh(float x) {
    const float kClamp = 7.90531110763549805f;
    float xc = fminf(fmaxf(x, -kClamp), kClamp);
    float x2 = xc * xc;
    float p = fmaf(x2, -2.76076847742355e-16f, 2.00018790482477e-13f);
    p = fmaf(x2, p, -8.60467152213735e-11f);
    p = fmaf(x2, p,  5.12229709037114e-08f);
    p = fmaf(x2, p,  1.48572235717979e-05f);
    p = fmaf(x2, p,  6.37261928875436e-04f);
    p = fmaf(x2, p,  4.89352455891786e-03f);
    float q = fmaf(x2, 1.19825839466702e-06f, 1.18534705686654e-04f);
    q = fmaf(x2, q, 2.26843463243900e-03f);
    q = fmaf(x2, q, 4.89352518554385e-03f);
    float r = (xc * p) / q;
    return (fabsf(x) < 0.0004f) ? x : r;
}

// Fast tanh for knum: tanh(z) = 1 - 2/(exp2(z*2log2e)+1), NR-refined rcp.
__device__ __forceinline__ float fast_tanh(float z) {
    float t = z * 2.8853900817779268f;          // 2/ln(2)
    t = fminf(fmaxf(t, -126.0f), 126.0f);       // keep e finite (NaN guard)
    float e; asm("ex2.approx.f32 %0, %1;" : "=f"(e) : "f"(t));
    float s = e + 1.0f;
    float r; asm("rcp.approx.f32 %0, %1;" : "=f"(r) : "f"(s));
    r = r * (2.0f - s * r);                      // Newton refinement
    return fmaf(-2.0f, r, 1.0f);
}

__device__ __forceinline__ float grid_lon_f(int k) {
    const float dlon = (float)((109.4132 - 95.987) / 200.0);
    return __fadd_rn(95.987f, __fmul_rn(dlon, (float)(k % GSZ)));
}
__device__ __forceinline__ float grid_lat_f(int k) {
    const float dlat = (float)((42.879 - 31.3039) / 200.0);
    return __fadd_rn(31.3039f, __fmul_rn(dlat, (float)(k / GSZ)));
}

#define D2R ((float)(3.14159265358979323846 / 180.0))

// ---------------------------------------------------------------------------
// Kernel 1: per-grid-cell agreement counts + fused packed-argmax atomic.
// DELTA vs measured R9: all hot smem streams use LDS.128 (ulonglong2),
// halving LSU issue count in the layer-2 loop.
// ---------------------------------------------------------------------------
__global__ __launch_bounds__(128)
void knum(const float* __restrict__ x,
          const float* __restrict__ w1, const float* __restrict__ b1,
          const float* __restrict__ g1, const float* __restrict__ be1,
          const float* __restrict__ m1, const float* __restrict__ v1,
          const float* __restrict__ w2, const float* __restrict__ b2,
          const float* __restrict__ g2, const float* __restrict__ be2,
          const float* __restrict__ m2, const float* __restrict__ v2,
          const float* __restrict__ w3, const float* __restrict__ b3)
{
    __shared__ __align__(16) float w2s[32][32];     // [i][j] = a2[j]*w2[i*32+j]
    __shared__ __align__(16) float o2s[32];
    __shared__ __align__(16) u64  w3pk[32][2];      // [j] = {pk(w3 c0,c1), pk(w3 c2,c3)}
    __shared__ float u1s[32], u2s[32], u0s[32];
    __shared__ float w3l[32], b3s[8];
    __shared__ int   wsum[2][4];

    const int t = threadIdx.x;

    if (t < 32) {
        float a1 = g1[t] / sqrtf(v1[t] + 1e-5f);
        u1s[t] = a1 * w1[t];
        u2s[t] = a1 * w1[32 + t];
        u0s[t] = fmaf(a1, b1[t], be1[t] - a1 * m1[t]);
        float a2 = g2[t] / sqrtf(v2[t] + 1e-5f);
        o2s[t] = fmaf(a2, b2[t], be2[t] - a2 * m2[t]);
        for (int i = 0; i < 32; i++) w2s[i][t] = a2 * w2[i * 32 + t];
        w3pk[t][0] = pk(w3[t * 5 + 0], w3[t * 5 + 1]);
        w3pk[t][1] = pk(w3[t * 5 + 2], w3[t * 5 + 3]);
        w3l[t]   = w3[t * 5 + 4];
        if (t < 5) b3s[t] = b3[t];
    }
    __syncthreads();

    // Per-point precompute.
    float lon2 = x[t * 4 + 0] * D2R;
    float lat2 = x[t * 4 + 1] * D2R;
    float s2 = sinf(lat2), c2 = cosf(lat2);
    float tc = x[t * 4 + 2] / 100.0f;
    int   pt = (int)x[t * 4 + 3];

    float p1[32];
#pragma unroll
    for (int j = 0; j < 32; j++) p1[j] = fmaf(tc, u2s[j], u0s[j]);

    const int lane = t & 31, wid = t >> 5;
    const int kbase = blockIdx.x * KB;

    // Row-constant haversine terms (all KB cells share one lat row).
    float lat1 = grid_lat_f(kbase) * D2R;
    float s1 = sinf(lat1), c1 = cosf(lat1);
    float t1 = c1 * s2, t2 = s1 * c2;     // B = t1 - t2*cdl
    float t3 = s1 * s2, t4 = c1 * c2;     // xv = t3 + t4*cdl

    const u64 lg01_0 = pk(b3s[0], b3s[1]);
    const u64 lg23_0 = pk(b3s[2], b3s[3]);
    const float lg4_0 = b3s[4];

    int bestEnc = 0;

#pragma unroll 1
    for (int kk = 0; kk < KB; kk++) {
        int k = kbase + kk;
        float lon1 = grid_lon_f(k) * D2R;
        float dl = lon2 - lon1;
        float sdl, cdl;
        sincosf(dl, &sdl, &cdl);
        float A  = c2 * sdl;
        float B  = t1 - t2 * cdl;
        float yv = sqrtf(A * A + B * B);
        float xv = t3 + t4 * cdl;
        float gd = atan2f(yv, xv) * 6371.0f;
        float d  = gd / 100.0f;

        // layer 1 (scalar fast tanh)
        float h1[32];
#pragma unroll
        for (int j = 0; j < 32; j++)
            h1[j] = fast_tanh(fmaf(d, u1s[j], p1[j]));

        // layer 2: packed accumulate; weights via LDS.128 (2 fma2 per load)
        u64 acc[16];
        const u64* o2p = (const u64*)o2s;
#pragma unroll
        for (int jj = 0; jj < 16; jj++) acc[jj] = o2p[jj];
#pragma unroll
        for (int i = 0; i < 32; i++) {
            u64 hd = pk(h1[i], h1[i]);
            const ulonglong2* wrow = (const ulonglong2*)(w2s[i]);
#pragma unroll
            for (int q = 0; q < 8; q++) {
                ulonglong2 w = wrow[q];
                acc[2 * q + 0] = fma2(hd, w.x, acc[2 * q + 0]);
                acc[2 * q + 1] = fma2(hd, w.y, acc[2 * q + 1]);
            }
        }

        // layer-2 tanh + logits; w3 pairs via LDS.128
        u64 lg01 = lg01_0, lg23 = lg23_0;
        float lg4 = lg4_0;
#pragma unroll
        for (int jj = 0; jj < 16; jj++) {
            float a0, a1v;
            upk(acc[jj], a0, a1v);
            float h20 = fast_tanh(a0);
            float h21 = fast_tanh(a1v);
            u64 hd0 = pk(h20, h20);
            u64 hd1 = pk(h21, h21);
            ulonglong2 w30 = *(const ulonglong2*)(w3pk[2 * jj + 0]);
            ulonglong2 w31 = *(const ulonglong2*)(w3pk[2 * jj + 1]);
            lg01 = fma2(hd0, w30.x, lg01);
            lg23 = fma2(hd0, w30.y, lg23);
            lg4  = fmaf(h20, w3l[2 * jj + 0], lg4);
            lg01 = fma2(hd1, w31.x, lg01);
            lg23 = fma2(hd1, w31.y, lg23);
            lg4  = fmaf(h21, w3l[2 * jj + 1], lg4);
        }

        float l0, l1, l2v, l3;
        upk(lg01, l0, l1);
        upk(lg23, l2v, l3);

        // first-max argmax over 5 logits
        int pid = 0; float bb = l0;
        if (l1  > bb) { bb = l1;  pid = 1; }
        if (l2v > bb) { bb = l2v; pid = 2; }
        if (l3  > bb) { bb = l3;  pid = 3; }
        if (lg4 > bb) { bb = lg4; pid = 4; }

        unsigned bal = __ballot_sync(0xffffffffu, pid == pt);
        int buf = kk & 1;
        if (lane == 0) wsum[buf][wid] = __popc(bal);
        __syncthreads();
        if (t == 0) {
            int cnt = wsum[buf][0] + wsum[buf][1] + wsum[buf][2] + wsum[buf][3];
            int enc = (cnt << 16) | (G2 - 1 - k);
            if (enc > bestEnc) bestEnc = enc;
        }
    }
    if (t == 0) atomicMax(&g_best, bestEnc);
}

// ---------------------------------------------------------------------------
// Kernel 2: decode best cell + finalize outputs (and reset g_best).
// (identical to measured R9 version: 22.5us)
// out: [0..127] class_, [128..383] ph (N x 2), [384] max_num, [385..386] pos
// ---------------------------------------------------------------------------
__global__ __launch_bounds__(128)
void kfinal(const float* __restrict__ x,
            const float* __restrict__ w1, const float* __restrict__ b1,
            const float* __restrict__ g1, const float* __restrict__ be1,
            const float* __restrict__ m1, const float* __restrict__ v1,
            const float* __restrict__ w2, const float* __restrict__ b2,
            const float* __restrict__ g2, const float* __restrict__ be2,
            const float* __restrict__ m2, const float* __restrict__ v2,
            const float* __restrict__ w3, const float* __restrict__ b3,
            float* __restrict__ out)
{
    __shared__ float w2sh[1024];
    __shared__ float w1sh[64], w3sh[160];
    __shared__ float p1sh[32 * 5];     // b1,g1,be1,m1,v1
    __shared__ float p2sh[32 * 5];     // b2,g2,be2,m2,v2
    __shared__ float b3s[5];
    __shared__ int sbest;
    const int t = threadIdx.x;

    if (t == 0) {
        sbest = g_best;
        g_best = 0;              // reset for next graph replay (deterministic)
    }
    for (int i = t; i < 1024; i += 128) w2sh[i] = w2[i];
    if (t < 64) w1sh[t] = w1[t];
    for (int i = t; i < 160; i += 128) w3sh[i] = w3[i];
    if (t < 32) {
        p1sh[t]       = b1[t];  p1sh[32 + t] = g1[t]; p1sh[64 + t] = be1[t];
        p1sh[96 + t]  = m1[t];  p1sh[128 + t] = v1[t];
        p2sh[t]       = b2[t];  p2sh[32 + t] = g2[t]; p2sh[64 + t] = be2[t];
        p2sh[96 + t]  = m2[t];  p2sh[128 + t] = v2[t];
    }
    if (t < 5) b3s[t] = b3[t];
    __syncthreads();

    const int best = sbest;
    const int bk = (G2 - 1) - (best & 0xFFFF);
    const int bn = best >> 16;

    if (t == 0) {
        out[384] = (float)bn;
        out[385] = grid_lon_f(bk);
        out[386] = grid_lat_f(bk);
    }

    {
        float lon2 = x[t * 4 + 0] * D2R;
        float lat2 = x[t * 4 + 1] * D2R;
        float s2 = sinf(lat2), c2 = cosf(lat2);
        float tc = x[t * 4 + 2] / 100.0f;

        float lat1 = grid_lat_f(bk) * D2R;
        float lon1 = grid_lon_f(bk) * D2R;
        float s1 = sinf(lat1), c1 = cosf(lat1);
        float dl  = lon2 - lon1;
        float sdl = sinf(dl), cdl = cosf(dl);
        float A  = c2 * sdl;
        float B  = c1 * s2 - s1 * c2 * cdl;
        float yv = sqrtf(A * A + B * B);
        float xv = s1 * s2 + c1 * c2 * cdl;
        float gd = atan2f(yv, xv) * 6371.0f;
        float d  = gd / 100.0f;

        float h1[32];
        for (int j = 0; j < 32; j++) {
            float z = d * w1sh[j] + tc * w1sh[32 + j] + p1sh[j];
            z = p1sh[32 + j] * (z - p1sh[96 + j]) / sqrtf(p1sh[128 + j] + 1e-5f) + p1sh[64 + j];
            h1[j] = xla_tanh(z);
        }
        float h2[32];
        for (int j = 0; j < 32; j++) {
            float z = p2sh[j];
            for (int i = 0; i < 32; i++) z += h1[i] * w2sh[i * 32 + j];
            z = p2sh[32 + j] * (z - p2sh[96 + j]) / sqrtf(p2sh[128 + j] + 1e-5f) + p2sh[64 + j];
            h2[j] = xla_tanh(z);
        }
        float lg[5];
        for (int c = 0; c < 5; c++) {
            float z = b3s[c];
            for (int j = 0; j < 32; j++) z += h2[j] * w3sh[j * 5 + c];
            lg[c] = z;
        }
        int pid = 0; float bb = lg[0];
        for (int c = 1; c < 5; c++) if (lg[c] > bb) { bb = lg[c]; pid = c; }

        out[t] = (float)pid;
        out[128 + 2 * t + 0] = d * 100.0f;
        out[128 + 2 * t + 1] = tc * 100.0f;
    }
}

// ---------------------------------------------------------------------------
extern "C" void kernel_launch(void* const* d_in, const int* in_sizes, int n_in,
                              void* d_out, int out_size)
{
    const float* x   = (const float*)d_in[0];
    const float* w1  = (const float*)d_in[1];
    const float* b1  = (const float*)d_in[2];
    const float* g1  = (const float*)d_in[3];
    const float* be1 = (const float*)d_in[4];
    const float* m1  = (const float*)d_in[5];
    const float* v1  = (const float*)d_in[6];
    const float* w2  = (const float*)d_in[7];
    const float* b2  = (const float*)d_in[8];
    const float* g2  = (const float*)d_in[9];
    const float* be2 = (const float*)d_in[10];
    const float* m2  = (const float*)d_in[11];
    const float* v2  = (const float*)d_in[12];
    const float* w3  = (const float*)d_in[13];
    const float* b3  = (const float*)d_in[14];
    float* out = (float*)d_out;

    knum<<<G2 / KB, 128>>>(x, w1, b1, g1, be1, m1, v1,
                           w2, b2, g2, be2, m2, v2, w3, b3);
    kfinal<<<1, 128>>>(x, w1, b1, g1, be1, m1, v1,
                       w2, b2, g2, be2, m2, v2, w3, b3, out);
}